// round 2
// baseline (speedup 1.0000x reference)
#include <cuda_runtime.h>
#include <math.h>

#define TT   8192
#define DIN  2048
#define DD   512
#define HH   512
#define AA   18
#define CANARY (-1.0f)

// ---------------- scratch (static device allocations; no cudaMalloc) ----------
__device__ float g_z1 [TT * DD];        // relu(x@W1+b1)
__device__ float g_z2 [TT * DD];        // relu(z1@W2+b2)
__device__ float g_X  [TT * 3 * HH];    // z2@Wg + bg[0]
__device__ float g_seq[TT * HH];        // GRU hidden states h[t]

// ---------------- helpers ----------------------------------------------------
__device__ __forceinline__ float ld_poll(const float* p) {
    float v;
    asm volatile("ld.global.cg.f32 %0, [%1];" : "=f"(v) : "l"(p));
    return v;
}
__device__ __forceinline__ void st_rel(float* p, float v) {
    asm volatile("st.global.cg.f32 [%0], %1;" :: "l"(p), "f"(v) : "memory");
}

// ---------------- canary fill -------------------------------------------------
__global__ void fill_canary_k(float* p, int n) {
    int i = blockIdx.x * blockDim.x + threadIdx.x;
    if (i < n) p[i] = CANARY;
}

// ---------------- 128x128x8 register-blocked SGEMM ---------------------------
// C[M,N] = op(A[M,K] @ B[K,N] + bias[N]);  op = relu if relu!=0
// requires M%128==0, N%128==0, K%8==0 (true for all three calls)
__global__ __launch_bounds__(256) void sgemm128(
    const float* __restrict__ A, const float* __restrict__ B,
    const float* __restrict__ bias, float* __restrict__ C,
    int M, int N, int K, int relu)
{
    __shared__ float As[8][128];
    __shared__ float Bs[8][128];
    int tid  = threadIdx.x;
    int brow = blockIdx.y * 128, bcol = blockIdx.x * 128;
    int aRow = tid >> 1,   aCol = (tid & 1) * 4;
    int bRow = tid >> 5,   bCol = (tid & 31) * 4;
    int trow = (tid >> 4) * 8, tcol = (tid & 15) * 8;

    const float* Ap = A + (size_t)(brow + aRow) * K + aCol;
    const float* Bp = B + (size_t)bRow * N + bcol + bCol;

    float acc[8][8];
#pragma unroll
    for (int i = 0; i < 8; i++)
#pragma unroll
        for (int j = 0; j < 8; j++) acc[i][j] = 0.f;

    for (int k0 = 0; k0 < K; k0 += 8) {
        float4 a4 = *(const float4*)Ap;  Ap += 8;
        float4 b4 = *(const float4*)Bp;  Bp += (size_t)8 * N;
        As[aCol + 0][aRow] = a4.x;
        As[aCol + 1][aRow] = a4.y;
        As[aCol + 2][aRow] = a4.z;
        As[aCol + 3][aRow] = a4.w;
        *(float4*)&Bs[bRow][bCol] = b4;
        __syncthreads();
#pragma unroll
        for (int kk = 0; kk < 8; kk++) {
            float fa[8], fb[8];
            *(float4*)&fa[0] = *(const float4*)&As[kk][trow];
            *(float4*)&fa[4] = *(const float4*)&As[kk][trow + 4];
            *(float4*)&fb[0] = *(const float4*)&Bs[kk][tcol];
            *(float4*)&fb[4] = *(const float4*)&Bs[kk][tcol + 4];
#pragma unroll
            for (int i = 0; i < 8; i++)
#pragma unroll
                for (int j = 0; j < 8; j++)
                    acc[i][j] = fmaf(fa[i], fb[j], acc[i][j]);
        }
        __syncthreads();
    }

#pragma unroll
    for (int i = 0; i < 8; i++) {
        float* cp = C + (size_t)(brow + trow + i) * N + bcol + tcol;
#pragma unroll
        for (int j = 0; j < 8; j++) {
            float v = acc[i][j] + bias[bcol + tcol + j];
            if (relu) v = v > 0.f ? v : 0.f;
            cp[j] = v;
        }
    }
}

// ---------------- GRU scan ----------------------------------------------------
// grid = 128 blocks x 128 threads. Warp w of block b owns hidden index
// i = 4*b + w and its 3 gate columns of Ug (z at i, r at 512+i, h at 1024+i).
// Lane l holds Ug[k, col] for k = l, l+32, ..., l+480 in registers.
// Step sync: seq[t] slots are canary-filled; readers spin on ld.global.cg.
__global__ __launch_bounds__(128, 1) void gru_scan_k(
    const float* __restrict__ X,   // [T, 3H] = z2@Wg + bg[0]
    const float* __restrict__ Ug,  // [H, 3H]
    const float* __restrict__ bg,  // [2, 3H]; row 1 = recurrent bias
    const float* __restrict__ h0,  // [1, H]
    float* __restrict__ seq)       // [T, H]
{
    const int w = threadIdx.x >> 5;
    const int l = threadIdx.x & 31;
    const int i = blockIdx.x * 4 + w;      // hidden index 0..511

    // register-resident weight slices
    float wz[16], wr[16], wh[16];
#pragma unroll
    for (int j = 0; j < 16; j++) {
        int k = l + 32 * j;
        wz[j] = Ug[(size_t)k * 1536 + i];
        wr[j] = Ug[(size_t)k * 1536 + 512 + i];
        wh[j] = Ug[(size_t)k * 1536 + 1024 + i];
    }
    float brz = 0.f, brr = 0.f, brh = 0.f;
    if (l == 0) {
        brz = bg[1536 + i];
        brr = bg[1536 + 512 + i];
        brh = bg[1536 + 1024 + i];
    }

    for (int t = 0; t < TT; t++) {
        const float* hp = t ? (seq + (size_t)(t - 1) * HH) : h0;

        // input projections for this step (lane 0 only; issued before the poll
        // so their latency hides under the spin)
        float xz = 0.f, xr = 0.f, xh = 0.f;
        if (l == 0) {
            const float* xp = X + (size_t)t * 1536 + i;
            xz = xp[0]; xr = xp[512]; xh = xp[1024];
        }

        // gather h[t-1]
        float hv[16];
#pragma unroll
        for (int j = 0; j < 16; j++) hv[j] = ld_poll(hp + l + 32 * j);
        float hi = 0.f;
        if (l == 0) hi = ld_poll(hp + i);

        if (t) {
            unsigned pend;
            do {
                bool bad = false;
#pragma unroll
                for (int j = 0; j < 16; j++) {
                    if (hv[j] == CANARY) {
                        hv[j] = ld_poll(hp + l + 32 * j);
                        bad |= (hv[j] == CANARY);
                    }
                }
                if (l == 0 && hi == CANARY) {
                    hi = ld_poll(hp + i);
                    bad |= (hi == CANARY);
                }
                pend = __ballot_sync(0xffffffffu, bad);
            } while (pend);
        }

        // partial dots (2 accumulators per gate to shorten FFMA dep chains)
        float az0 = 0.f, az1 = 0.f, ar0 = 0.f, ar1 = 0.f, ah0 = 0.f, ah1 = 0.f;
#pragma unroll
        for (int j = 0; j < 16; j += 2) {
            az0 = fmaf(wz[j],     hv[j],     az0);
            az1 = fmaf(wz[j + 1], hv[j + 1], az1);
            ar0 = fmaf(wr[j],     hv[j],     ar0);
            ar1 = fmaf(wr[j + 1], hv[j + 1], ar1);
            ah0 = fmaf(wh[j],     hv[j],     ah0);
            ah1 = fmaf(wh[j + 1], hv[j + 1], ah1);
        }
        float az = az0 + az1, ar = ar0 + ar1, ah = ah0 + ah1;

        // butterfly reduce across 32 lanes
#pragma unroll
        for (int o = 16; o > 0; o >>= 1) {
            az += __shfl_xor_sync(0xffffffffu, az, o);
            ar += __shfl_xor_sync(0xffffffffu, ar, o);
            ah += __shfl_xor_sync(0xffffffffu, ah, o);
        }

        if (l == 0) {
            float rz = az + brz, rr = ar + brr, rh = ah + brh;
            float zt = 1.f / (1.f + __expf(-(xz + rz)));
            float rt = 1.f / (1.f + __expf(-(xr + rr)));
            float hh = 1.f / (1.f + __expf(-(xh + rt * rh)));
            float hn = zt * hi + (1.f - zt) * hh;
            st_rel(seq + (size_t)t * HH + i, hn);
        }
    }
}

// ---------------- policy / value heads ---------------------------------------
// one warp per timestep: lanes 0..17 = policy logits, lane 18 = value.
__global__ __launch_bounds__(256) void head_k(
    const float* __restrict__ seq,
    const float* __restrict__ Wp, const float* __restrict__ bp,
    const float* __restrict__ Wv, const float* __restrict__ bv,
    float* __restrict__ out)
{
    int warp = blockIdx.x * (blockDim.x >> 5) + (threadIdx.x >> 5);
    int l = threadIdx.x & 31;
    if (warp >= TT) return;
    const float* s = seq + (size_t)warp * HH;

    const float* wptr;
    int stride;
    float acc;
    if (l < AA)       { wptr = Wp + l; stride = AA; acc = bp[l]; }
    else if (l == AA) { wptr = Wv;     stride = 1;  acc = bv[0]; }
    else              { wptr = Wp;     stride = 0;  acc = 0.f; }

#pragma unroll 8
    for (int k = 0; k < HH; k++)
        acc = fmaf(s[k], wptr[(size_t)k * stride], acc);

    float lv = (l < AA) ? acc : -INFINITY;
    float m = lv;
#pragma unroll
    for (int o = 16; o > 0; o >>= 1) m = fmaxf(m, __shfl_xor_sync(0xffffffffu, m, o));
    float e = (l < AA) ? __expf(acc - m) : 0.f;
    float ssum = e;
#pragma unroll
    for (int o = 16; o > 0; o >>= 1) ssum += __shfl_xor_sync(0xffffffffu, ssum, o);

    if (l < AA)  out[(size_t)warp * AA + l] = e / ssum;       // policy
    if (l == AA) out[(size_t)TT * AA + warp] = acc;           // value
}

__global__ void ht_k(const float* __restrict__ seq, float* __restrict__ out) {
    int i = threadIdx.x;
    out[(size_t)TT * (AA + 1) + i] = seq[(size_t)(TT - 1) * HH + i];
}

// ---------------- launch ------------------------------------------------------
extern "C" void kernel_launch(void* const* d_in, const int* in_sizes, int n_in,
                              void* d_out, int out_size)
{
    const float* x  = (const float*)d_in[0];
    const float* h0 = (const float*)d_in[1];
    const float* W1 = (const float*)d_in[2];
    const float* b1 = (const float*)d_in[3];
    const float* W2 = (const float*)d_in[4];
    const float* b2 = (const float*)d_in[5];
    const float* Wg = (const float*)d_in[6];
    const float* Ug = (const float*)d_in[7];
    const float* bg = (const float*)d_in[8];
    const float* Wp = (const float*)d_in[9];
    const float* bp = (const float*)d_in[10];
    const float* Wv = (const float*)d_in[11];
    const float* bv = (const float*)d_in[12];
    float* out = (float*)d_out;

    float *z1, *z2, *X, *seq;
    cudaGetSymbolAddress((void**)&z1,  g_z1);
    cudaGetSymbolAddress((void**)&z2,  g_z2);
    cudaGetSymbolAddress((void**)&X,   g_X);
    cudaGetSymbolAddress((void**)&seq, g_seq);

    // 0) canary-fill seq (graph replays need a fresh canary every launch)
    fill_canary_k<<<(TT * HH + 255) / 256, 256>>>(seq, TT * HH);

    // 1) MLP front-end + GRU input projection
    dim3 g1(DD / 128, TT / 128);
    sgemm128<<<g1, 256>>>(x,  W1, b1, z1, TT, DD, DIN, 1);
    sgemm128<<<g1, 256>>>(z1, W2, b2, z2, TT, DD, DD, 1);
    dim3 g3((3 * HH) / 128, TT / 128);
    sgemm128<<<g3, 256>>>(z2, Wg, bg /*row 0*/, X, TT, 3 * HH, DD, 0);

    // 2) sequential GRU scan (persistent, flag-free canary sync)
    gru_scan_k<<<128, 128>>>(X, Ug, bg, h0, seq);

    // 3) heads + final hidden state
    head_k<<<(TT * 32 + 255) / 256, 256>>>(seq, Wp, bp, Wv, bv, out);
    ht_k<<<1, HH>>>(seq, out);
}

// round 4
// speedup vs baseline: 6.2981x; 6.2981x over previous
#include <cuda_runtime.h>
#include <math.h>

#define TT   8192
#define DIN  2048
#define DD   512
#define HH   512
#define AA   18

#define CL   16      // cluster size (CTAs)
#define THR  512     // threads per CTA
#define NW   (THR/32)

// ---------------- scratch ------------------------------------------------------
__device__ float g_z1 [TT * DD];
__device__ float g_z2 [TT * DD];
__device__ float g_X  [TT * 3 * HH];
__device__ float g_seq[TT * HH];

// ---------------- asm helpers --------------------------------------------------
__device__ __forceinline__ unsigned smem_u32(const void* p) {
    unsigned a;
    asm("{ .reg .u64 t; cvta.to.shared.u64 t, %1; cvt.u32.u64 %0, t; }" : "=r"(a) : "l"(p));
    return a;
}
__device__ __forceinline__ unsigned ctarank() {
    unsigned r; asm("mov.u32 %0, %%cluster_ctarank;" : "=r"(r)); return r;
}
__device__ __forceinline__ unsigned mapa_u32(unsigned addr, unsigned rank) {
    unsigned r; asm("mapa.shared::cluster.u32 %0, %1, %2;" : "=r"(r) : "r"(addr), "r"(rank));
    return r;
}
__device__ __forceinline__ void st_cluster_f32(unsigned addr, float v) {
    asm volatile("st.shared::cluster.f32 [%0], %1;" :: "r"(addr), "f"(v) : "memory");
}
__device__ __forceinline__ unsigned long long pk2(float lo, float hi) {
    unsigned long long r; asm("mov.b64 %0, {%1,%2};" : "=l"(r) : "f"(lo), "f"(hi)); return r;
}
__device__ __forceinline__ void up2(unsigned long long v, float& lo, float& hi) {
    asm("mov.b64 {%0,%1}, %2;" : "=f"(lo), "=f"(hi) : "l"(v));
}
__device__ __forceinline__ unsigned long long ffma2(unsigned long long a,
                                                    unsigned long long b,
                                                    unsigned long long c) {
    unsigned long long d;
    asm("fma.rn.f32x2 %0, %1, %2, %3;" : "=l"(d) : "l"(a), "l"(b), "l"(c));
    return d;
}
__device__ __forceinline__ float sigmoidf_fast(float x) {
    return 1.f / (1.f + __expf(-x));
}

// ---------------- 128x128x8 register-blocked SGEMM -----------------------------
__global__ __launch_bounds__(256) void sgemm128(
    const float* __restrict__ A, const float* __restrict__ B,
    const float* __restrict__ bias, float* __restrict__ C,
    int M, int N, int K, int relu)
{
    __shared__ float As[8][128];
    __shared__ float Bs[8][128];
    int tid  = threadIdx.x;
    int brow = blockIdx.y * 128, bcol = blockIdx.x * 128;
    int aRow = tid >> 1,   aCol = (tid & 1) * 4;
    int bRow = tid >> 5,   bCol = (tid & 31) * 4;
    int trow = (tid >> 4) * 8, tcol = (tid & 15) * 8;

    const float* Ap = A + (size_t)(brow + aRow) * K + aCol;
    const float* Bp = B + (size_t)bRow * N + bcol + bCol;

    float acc[8][8];
#pragma unroll
    for (int i = 0; i < 8; i++)
#pragma unroll
        for (int j = 0; j < 8; j++) acc[i][j] = 0.f;

    for (int k0 = 0; k0 < K; k0 += 8) {
        float4 a4 = *(const float4*)Ap;  Ap += 8;
        float4 b4 = *(const float4*)Bp;  Bp += (size_t)8 * N;
        As[aCol + 0][aRow] = a4.x;
        As[aCol + 1][aRow] = a4.y;
        As[aCol + 2][aRow] = a4.z;
        As[aCol + 3][aRow] = a4.w;
        *(float4*)&Bs[bRow][bCol] = b4;
        __syncthreads();
#pragma unroll
        for (int kk = 0; kk < 8; kk++) {
            float fa[8], fb[8];
            *(float4*)&fa[0] = *(const float4*)&As[kk][trow];
            *(float4*)&fa[4] = *(const float4*)&As[kk][trow + 4];
            *(float4*)&fb[0] = *(const float4*)&Bs[kk][tcol];
            *(float4*)&fb[4] = *(const float4*)&Bs[kk][tcol + 4];
#pragma unroll
            for (int i = 0; i < 8; i++)
#pragma unroll
                for (int j = 0; j < 8; j++)
                    acc[i][j] = fmaf(fa[i], fb[j], acc[i][j]);
        }
        __syncthreads();
    }

#pragma unroll
    for (int i = 0; i < 8; i++) {
        float* cp = C + (size_t)(brow + trow + i) * N + bcol + tcol;
#pragma unroll
        for (int j = 0; j < 8; j++) {
            float v = acc[i][j] + bias[bcol + tcol + j];
            if (relu) v = v > 0.f ? v : 0.f;
            cp[j] = v;
        }
    }
}

// ---------------- GRU scan: 16-CTA cluster, DSMEM h exchange -------------------
// 256 warps cluster-wide. Warp W owns hidden indices i0=2W, i1=2W+1 (6 gate
// columns of Ug), weights register-resident as packed f32x2. h double-buffered
// in SMEM; each step every warp pushes its 2 new h values to all 16 CTAs via
// st.shared::cluster, then a cluster barrier (arrive=release / wait=acquire)
// publishes them.
__global__ void __cluster_dims__(CL, 1, 1) __launch_bounds__(THR, 1)
gru_cluster_k(const float* __restrict__ X,   // [T, 3H]
              const float* __restrict__ Ug,  // [H, 3H]
              const float* __restrict__ bg,  // [2, 3H]
              const float* __restrict__ h0,  // [1, H]
              float* __restrict__ seq)       // [T, H]
{
    __shared__ float hbuf[2][HH];

    const int tid = threadIdx.x;
    const int wid = tid >> 5;
    const int l   = tid & 31;
    const unsigned rank = ctarank();
    const int W  = (int)rank * NW + wid;   // 0..255
    const int i0 = 2 * W;
    const int i1 = i0 + 1;

    // ---- register-resident packed weights: wp[g][j] covers k = 2l+64j, 2l+64j+1
    unsigned long long wp[6][8];
    {
        const int cols[6] = { i0, 512 + i0, 1024 + i0, i1, 512 + i1, 1024 + i1 };
#pragma unroll
        for (int j = 0; j < 8; j++) {
            int k = 2 * l + 64 * j;
            const float* r0 = Ug + (size_t)k * 1536;
            const float* r1 = r0 + 1536;
#pragma unroll
            for (int g = 0; g < 6; g++)
                wp[g][j] = pk2(r0[cols[g]], r1[cols[g]]);
        }
    }

    // recurrent biases for this lane's hidden index (lanes 0,1 only meaningful)
    const int bi = (l < 2) ? (i0 + l) : i0;
    float brz = bg[1536 + bi];
    float brr = bg[1536 + 512 + bi];
    float brh = bg[1536 + 1024 + bi];

    // precompute remote store addresses (both buffers) for this lane's push
    const int  my_idx = (l < 16) ? i0 : i1;
    const unsigned peer = (unsigned)(l & 15);
    const unsigned ra0 = mapa_u32(smem_u32(&hbuf[0][my_idx]), peer);
    const unsigned ra1 = mapa_u32(smem_u32(&hbuf[1][my_idx]), peer);

    // init h[-1] = h0 into buffer 0
    hbuf[0][tid] = h0[tid];
    __syncthreads();
    asm volatile("barrier.cluster.arrive.aligned;" ::: "memory");
    asm volatile("barrier.cluster.wait.aligned;"   ::: "memory");

    for (int t = 0; t < TT; t++) {
        const int p = t & 1;

        // input projections (lanes 0,1) — issue early, latency hides under dot
        float xz = 0.f, xr = 0.f, xh = 0.f;
        if (l < 2) {
            const float* xp = X + (size_t)t * 1536 + (i0 + l);
            xz = xp[0]; xr = xp[512]; xh = xp[1024];
        }
        float hprev = hbuf[p][i0 + (l & 1)];

        // packed dot products
        unsigned long long a0 = 0, a1 = 0, a2 = 0, a3 = 0, a4 = 0, a5 = 0;
#pragma unroll
        for (int j = 0; j < 8; j++) {
            unsigned long long h2 =
                *(const unsigned long long*)&hbuf[p][2 * l + 64 * j];
            a0 = ffma2(wp[0][j], h2, a0);
            a1 = ffma2(wp[1][j], h2, a1);
            a2 = ffma2(wp[2][j], h2, a2);
            a3 = ffma2(wp[3][j], h2, a3);
            a4 = ffma2(wp[4][j], h2, a4);
            a5 = ffma2(wp[5][j], h2, a5);
        }
        float s[6];
        { float lo, hi;
          up2(a0, lo, hi); s[0] = lo + hi;
          up2(a1, lo, hi); s[1] = lo + hi;
          up2(a2, lo, hi); s[2] = lo + hi;
          up2(a3, lo, hi); s[3] = lo + hi;
          up2(a4, lo, hi); s[4] = lo + hi; 
          up2(a5, lo, hi); s[5] = lo + hi; }

        // butterfly reduce (6 interleaved chains)
#pragma unroll
        for (int o = 16; o > 0; o >>= 1) {
#pragma unroll
            for (int g = 0; g < 6; g++)
                s[g] += __shfl_xor_sync(0xffffffffu, s[g], o);
        }

        // gate math (lanes 0 and 1 each finish one hidden index)
        const int odd = l & 1;
        float az = odd ? s[3] : s[0];
        float ar = odd ? s[4] : s[1];
        float ah = odd ? s[5] : s[2];
        float zt = sigmoidf_fast(xz + az + brz);
        float rt = sigmoidf_fast(xr + ar + brr);
        float hc = sigmoidf_fast(xh + rt * (ah + brh));
        float hn = zt * hprev + (1.f - zt) * hc;

        // broadcast the two new values, push to all 16 CTAs (other buffer)
        float hn0 = __shfl_sync(0xffffffffu, hn, 0);
        float hn1 = __shfl_sync(0xffffffffu, hn, 1);
        float hv  = (l < 16) ? hn0 : hn1;
        st_cluster_f32(p ? ra0 : ra1, hv);

        // persist to global sequence (read by heads kernel after scan)
        if (l < 2) seq[(size_t)t * HH + i0 + l] = hn;

        // publish step: arrive(release) + wait(acquire)
        asm volatile("barrier.cluster.arrive.aligned;" ::: "memory");
        asm volatile("barrier.cluster.wait.aligned;"   ::: "memory");
    }
}

// ---------------- policy / value heads -----------------------------------------
__global__ __launch_bounds__(256) void head_k(
    const float* __restrict__ seq,
    const float* __restrict__ Wp, const float* __restrict__ bp,
    const float* __restrict__ Wv, const float* __restrict__ bv,
    float* __restrict__ out)
{
    int warp = blockIdx.x * (blockDim.x >> 5) + (threadIdx.x >> 5);
    int l = threadIdx.x & 31;
    if (warp >= TT) return;
    const float* s = seq + (size_t)warp * HH;

    const float* wptr;
    int stride;
    float acc;
    if (l < AA)       { wptr = Wp + l; stride = AA; acc = bp[l]; }
    else if (l == AA) { wptr = Wv;     stride = 1;  acc = bv[0]; }
    else              { wptr = Wp;     stride = 0;  acc = 0.f; }

#pragma unroll 8
    for (int k = 0; k < HH; k++)
        acc = fmaf(s[k], wptr[(size_t)k * stride], acc);

    float lv = (l < AA) ? acc : -INFINITY;
    float m = lv;
#pragma unroll
    for (int o = 16; o > 0; o >>= 1) m = fmaxf(m, __shfl_xor_sync(0xffffffffu, m, o));
    float e = (l < AA) ? __expf(acc - m) : 0.f;
    float ssum = e;
#pragma unroll
    for (int o = 16; o > 0; o >>= 1) ssum += __shfl_xor_sync(0xffffffffu, ssum, o);

    if (l < AA)  out[(size_t)warp * AA + l] = e / ssum;       // policy
    if (l == AA) out[(size_t)TT * AA + warp] = acc;           // value
}

__global__ void ht_k(const float* __restrict__ seq, float* __restrict__ out) {
    int i = threadIdx.x;
    out[(size_t)TT * (AA + 1) + i] = seq[(size_t)(TT - 1) * HH + i];
}

// ---------------- launch --------------------------------------------------------
extern "C" void kernel_launch(void* const* d_in, const int* in_sizes, int n_in,
                              void* d_out, int out_size)
{
    const float* x  = (const float*)d_in[0];
    const float* h0 = (const float*)d_in[1];
    const float* W1 = (const float*)d_in[2];
    const float* b1 = (const float*)d_in[3];
    const float* W2 = (const float*)d_in[4];
    const float* b2 = (const float*)d_in[5];
    const float* Wg = (const float*)d_in[6];
    const float* Ug = (const float*)d_in[7];
    const float* bg = (const float*)d_in[8];
    const float* Wp = (const float*)d_in[9];
    const float* bp = (const float*)d_in[10];
    const float* Wv = (const float*)d_in[11];
    const float* bv = (const float*)d_in[12];
    float* out = (float*)d_out;

    float *z1, *z2, *X, *seq;
    cudaGetSymbolAddress((void**)&z1,  g_z1);
    cudaGetSymbolAddress((void**)&z2,  g_z2);
    cudaGetSymbolAddress((void**)&X,   g_X);
    cudaGetSymbolAddress((void**)&seq, g_seq);

    // 16-CTA cluster needs the non-portable size opt-in (idempotent)
    cudaFuncSetAttribute(gru_cluster_k,
                         cudaFuncAttributeNonPortableClusterSizeAllowed, 1);

    // 1) MLP front-end + GRU input projection
    dim3 g1(DD / 128, TT / 128);
    sgemm128<<<g1, 256>>>(x,  W1, b1, z1, TT, DD, DIN, 1);
    sgemm128<<<g1, 256>>>(z1, W2, b2, z2, TT, DD, DD, 1);
    dim3 g3((3 * HH) / 128, TT / 128);
    sgemm128<<<g3, 256>>>(z2, Wg, bg /*row 0*/, X, TT, 3 * HH, DD, 0);

    // 2) sequential GRU scan (single 16-CTA cluster, DSMEM exchange)
    gru_cluster_k<<<CL, THR>>>(X, Ug, bg, h0, seq);

    // 3) heads + final hidden state
    head_k<<<(TT * 32 + 255) / 256, 256>>>(seq, Wp, bp, Wv, bv, out);
    ht_k<<<1, HH>>>(seq, out);
}

// round 8
// speedup vs baseline: 8.5515x; 1.3578x over previous
#include <cuda_runtime.h>
#include <math.h>

#define TT   8192
#define DIN  2048
#define DD   512
#define HH   512
#define AA   18

#define CL   16      // cluster size (CTAs)
#define THR  512     // threads per CTA
#define NW   (THR/32)

// ---------------- scratch ------------------------------------------------------
__device__ float g_z1 [TT * DD];
__device__ float g_z2 [TT * DD];
__device__ float g_X  [TT * 3 * HH];
__device__ float g_seq[TT * HH];

// ---------------- asm helpers --------------------------------------------------
__device__ __forceinline__ unsigned smem_u32(const void* p) {
    unsigned a;
    asm("{ .reg .u64 t; cvta.to.shared.u64 t, %1; cvt.u32.u64 %0, t; }" : "=r"(a) : "l"(p));
    return a;
}
__device__ __forceinline__ unsigned ctarank() {
    unsigned r; asm("mov.u32 %0, %%cluster_ctarank;" : "=r"(r)); return r;
}
__device__ __forceinline__ unsigned mapa_u32(unsigned addr, unsigned rank) {
    unsigned r; asm("mapa.shared::cluster.u32 %0, %1, %2;" : "=r"(r) : "r"(addr), "r"(rank));
    return r;
}
__device__ __forceinline__ unsigned long long pk2(float lo, float hi) {
    unsigned long long r; asm("mov.b64 %0, {%1,%2};" : "=l"(r) : "f"(lo), "f"(hi)); return r;
}
__device__ __forceinline__ void up2(unsigned long long v, float& lo, float& hi) {
    asm("mov.b64 {%0,%1}, %2;" : "=f"(lo), "=f"(hi) : "l"(v));
}
__device__ __forceinline__ unsigned long long ffma2(unsigned long long a,
                                                    unsigned long long b,
                                                    unsigned long long c) {
    unsigned long long d;
    asm("fma.rn.f32x2 %0, %1, %2, %3;" : "=l"(d) : "l"(a), "l"(b), "l"(c));
    return d;
}
__device__ __forceinline__ float sigmoidf_fast(float x) {
    return 1.f / (1.f + __expf(-x));
}
// mbarrier primitives
__device__ __forceinline__ void mbar_init(unsigned addr, unsigned cnt) {
    asm volatile("mbarrier.init.shared::cta.b64 [%0], %1;" :: "r"(addr), "r"(cnt) : "memory");
}
__device__ __forceinline__ void mbar_arm(unsigned addr, unsigned txbytes) {
    asm volatile("mbarrier.arrive.expect_tx.shared::cta.b64 _, [%0], %1;"
                 :: "r"(addr), "r"(txbytes) : "memory");
}
__device__ __forceinline__ void mbar_wait(unsigned addr, unsigned parity) {
    asm volatile(
        "{\n\t.reg .pred P;\n"
        "LW_%=:\n\t"
        "mbarrier.try_wait.parity.acquire.cluster.shared::cta.b64 P, [%0], %1, 0x989680;\n\t"
        "@P bra LD_%=;\n\t"
        "bra LW_%=;\n"
        "LD_%=:\n\t}"
        :: "r"(addr), "r"(parity) : "memory");
}
__device__ __forceinline__ void st_async64(unsigned daddr, unsigned long long v,
                                           unsigned maddr) {
    asm volatile("st.async.shared::cluster.mbarrier::complete_tx::bytes.b64 [%0], %1, [%2];"
                 :: "r"(daddr), "l"(v), "r"(maddr) : "memory");
}

// ---------------- 128x128x8 register-blocked SGEMM -----------------------------
__global__ __launch_bounds__(256) void sgemm128(
    const float* __restrict__ A, const float* __restrict__ B,
    const float* __restrict__ bias, float* __restrict__ C,
    int M, int N, int K, int relu)
{
    __shared__ float As[8][128];
    __shared__ float Bs[8][128];
    int tid  = threadIdx.x;
    int brow = blockIdx.y * 128, bcol = blockIdx.x * 128;
    int aRow = tid >> 1,   aCol = (tid & 1) * 4;
    int bRow = tid >> 5,   bCol = (tid & 31) * 4;
    int trow = (tid >> 4) * 8, tcol = (tid & 15) * 8;

    const float* Ap = A + (size_t)(brow + aRow) * K + aCol;
    const float* Bp = B + (size_t)bRow * N + bcol + bCol;

    float acc[8][8];
#pragma unroll
    for (int i = 0; i < 8; i++)
#pragma unroll
        for (int j = 0; j < 8; j++) acc[i][j] = 0.f;

    for (int k0 = 0; k0 < K; k0 += 8) {
        float4 a4 = *(const float4*)Ap;  Ap += 8;
        float4 b4 = *(const float4*)Bp;  Bp += (size_t)8 * N;
        As[aCol + 0][aRow] = a4.x;
        As[aCol + 1][aRow] = a4.y;
        As[aCol + 2][aRow] = a4.z;
        As[aCol + 3][aRow] = a4.w;
        *(float4*)&Bs[bRow][bCol] = b4;
        __syncthreads();
#pragma unroll
        for (int kk = 0; kk < 8; kk++) {
            float fa[8], fb[8];
            *(float4*)&fa[0] = *(const float4*)&As[kk][trow];
            *(float4*)&fa[4] = *(const float4*)&As[kk][trow + 4];
            *(float4*)&fb[0] = *(const float4*)&Bs[kk][tcol];
            *(float4*)&fb[4] = *(const float4*)&Bs[kk][tcol + 4];
#pragma unroll
            for (int i = 0; i < 8; i++)
#pragma unroll
                for (int j = 0; j < 8; j++)
                    acc[i][j] = fmaf(fa[i], fb[j], acc[i][j]);
        }
        __syncthreads();
    }

#pragma unroll
    for (int i = 0; i < 8; i++) {
        float* cp = C + (size_t)(brow + trow + i) * N + bcol + tcol;
#pragma unroll
        for (int j = 0; j < 8; j++) {
            float v = acc[i][j] + bias[bcol + tcol + j];
            if (relu) v = v > 0.f ? v : 0.f;
            cp[j] = v;
        }
    }
}

// ---------------- GRU scan: 16-CTA cluster, st.async + mbarrier ----------------
// 256 warps cluster-wide; warp W owns hidden i0=2W, i1=2W+1 (6 gate columns),
// weights register-resident packed f32x2. h double-buffered in SMEM; each step
// every warp pushes its packed (h[i0],h[i1]) to all 16 CTAs via st.async.b64
// with mbarrier complete_tx; consumers try_wait on their local mbarrier
// (2048 expected bytes). No cluster-wide barrier inside the loop.
__global__ void __cluster_dims__(CL, 1, 1) __launch_bounds__(THR, 1)
gru_cluster_k(const float* __restrict__ X,   // [T, 3H]
              const float* __restrict__ Ug,  // [H, 3H]
              const float* __restrict__ bg,  // [2, 3H]
              const float* __restrict__ h0,  // [1, H]
              float* __restrict__ seq)       // [T, H]
{
    __shared__ __align__(16) float hbuf[2][HH];
    __shared__ __align__(8) unsigned long long mbar[2];

    const int tid = threadIdx.x;
    const int wid = tid >> 5;
    const int l   = tid & 31;
    const unsigned rank = ctarank();
    const int W  = (int)rank * NW + wid;   // 0..255
    const int i0 = 2 * W;
    const int half = l >> 4;               // 0: finalize i0, 1: finalize i1
    const int col  = i0 + half;            // hidden index this lane finalizes

    // ---- register-resident packed weights: wp[g][j] covers k = 2l+64j, +1
    unsigned long long wp[6][8];
    {
        const int i1 = i0 + 1;
        const int cols[6] = { i0, 512 + i0, 1024 + i0, i1, 512 + i1, 1024 + i1 };
#pragma unroll
        for (int j = 0; j < 8; j++) {
            int k = 2 * l + 64 * j;
            const float* r0 = Ug + (size_t)k * 1536;
            const float* r1 = r0 + 1536;
#pragma unroll
            for (int g = 0; g < 6; g++)
                wp[g][j] = pk2(r0[cols[g]], r1[cols[g]]);
        }
    }

    // recurrent biases for this lane's finalized column
    const float brz = bg[1536 + col];
    const float brr = bg[1536 + 512 + col];
    const float brh = bg[1536 + 1024 + col];

    // remote addresses: lane l (<16) pushes packed (h[i0],h[i1]) to peer l
    const unsigned peer = (unsigned)(l & 15);
    const unsigned rd0 = mapa_u32(smem_u32(&hbuf[0][i0]), peer);
    const unsigned rd1 = mapa_u32(smem_u32(&hbuf[1][i0]), peer);
    const unsigned rm0 = mapa_u32(smem_u32(&mbar[0]), peer);
    const unsigned rm1 = mapa_u32(smem_u32(&mbar[1]), peer);
    const unsigned lm0 = smem_u32(&mbar[0]);
    const unsigned lm1 = smem_u32(&mbar[1]);

    // init: mbarriers + h[-1] into buffer 0
    if (tid == 0) {
        mbar_init(lm0, 1);
        mbar_init(lm1, 1);
        mbar_arm(lm0, 2048);   // phase 0 of each buffer
        mbar_arm(lm1, 2048);
        asm volatile("fence.mbarrier_init.release.cluster;" ::: "memory");
    }
    hbuf[0][tid] = h0[tid];
    __syncthreads();
    asm volatile("barrier.cluster.arrive.aligned;" ::: "memory");
    asm volatile("barrier.cluster.wait.aligned;"   ::: "memory");

    unsigned ph0 = 0, ph1 = 0;

    for (int t = 0; t < TT; t++) {
        const int p = t & 1;

        // prefetch input projections (LDG issued before the wait)
        const float* xp = X + (size_t)t * 1536 + col;
        float xz = xp[0], xr = xp[512], xh = xp[1024];

        // wait for h[t-1] bytes, then re-arm this buffer's next phase
        if (t) {
            if (p) { mbar_wait(lm1, ph1); ph1 ^= 1; if (tid == 0) mbar_arm(lm1, 2048); }
            else   { mbar_wait(lm0, ph0); ph0 ^= 1; if (tid == 0) mbar_arm(lm0, 2048); }
        }

        const float hprev = hbuf[p][col];

        // packed dot products (6 independent chains, depth 8)
        unsigned long long a0 = 0, a1 = 0, a2 = 0, a3 = 0, a4 = 0, a5 = 0;
#pragma unroll
        for (int j = 0; j < 8; j++) {
            unsigned long long h2 =
                *(const unsigned long long*)&hbuf[p][2 * l + 64 * j];
            a0 = ffma2(wp[0][j], h2, a0);
            a1 = ffma2(wp[1][j], h2, a1);
            a2 = ffma2(wp[2][j], h2, a2);
            a3 = ffma2(wp[3][j], h2, a3);
            a4 = ffma2(wp[4][j], h2, a4);
            a5 = ffma2(wp[5][j], h2, a5);
        }
        float s0, s1, s2, s3, s4, s5;
        { float lo, hi;
          up2(a0, lo, hi); s0 = lo + hi;
          up2(a1, lo, hi); s1 = lo + hi;
          up2(a2, lo, hi); s2 = lo + hi;
          up2(a3, lo, hi); s3 = lo + hi;
          up2(a4, lo, hi); s4 = lo + hi;
          up2(a5, lo, hi); s5 = lo + hi; }

        // folded warp reduction:
        // stage 1 (offset 16) on all six sums -> halves are redundant,
        // then each half reduces only its own gate triple (offsets 8..1).
        s0 += __shfl_xor_sync(0xffffffffu, s0, 16);
        s1 += __shfl_xor_sync(0xffffffffu, s1, 16);
        s2 += __shfl_xor_sync(0xffffffffu, s2, 16);
        s3 += __shfl_xor_sync(0xffffffffu, s3, 16);
        s4 += __shfl_xor_sync(0xffffffffu, s4, 16);
        s5 += __shfl_xor_sync(0xffffffffu, s5, 16);
        float uz = half ? s3 : s0;
        float ur = half ? s4 : s1;
        float uh = half ? s5 : s2;
#pragma unroll
        for (int o = 8; o > 0; o >>= 1) {
            uz += __shfl_xor_sync(0xffffffffu, uz, o);
            ur += __shfl_xor_sync(0xffffffffu, ur, o);
            uh += __shfl_xor_sync(0xffffffffu, uh, o);
        }

        // gate math (lanes 0-15 finalize i0, lanes 16-31 finalize i1)
        const float zt = sigmoidf_fast(xz + uz + brz);
        const float rt = sigmoidf_fast(xr + ur + brr);
        const float hc = sigmoidf_fast(xh + rt * (uh + brh));
        const float hn = zt * hprev + (1.f - zt) * hc;

        // persist to global sequence (one lane per column)
        if ((l & 15) == 0) seq[(size_t)t * HH + col] = hn;

        // pair (h[i0], h[i1]) and push to all 16 CTAs' other buffer
        const float hn1 = __shfl_down_sync(0xffffffffu, hn, 16);
        if (l < 16 && t != TT - 1) {
            unsigned long long v = pk2(hn, hn1);
            if (p) st_async64(rd0, v, rm0);   // next buffer = 0
            else   st_async64(rd1, v, rm1);   // next buffer = 1
        }
    }

    asm volatile("barrier.cluster.arrive.aligned;" ::: "memory");
    asm volatile("barrier.cluster.wait.aligned;"   ::: "memory");
}

// ---------------- policy / value heads -----------------------------------------
__global__ __launch_bounds__(256) void head_k(
    const float* __restrict__ seq,
    const float* __restrict__ Wp, const float* __restrict__ bp,
    const float* __restrict__ Wv, const float* __restrict__ bv,
    float* __restrict__ out)
{
    int warp = blockIdx.x * (blockDim.x >> 5) + (threadIdx.x >> 5);
    int l = threadIdx.x & 31;
    if (warp >= TT) return;
    const float* s = seq + (size_t)warp * HH;

    const float* wptr;
    int stride;
    float acc;
    if (l < AA)       { wptr = Wp + l; stride = AA; acc = bp[l]; }
    else if (l == AA) { wptr = Wv;     stride = 1;  acc = bv[0]; }
    else              { wptr = Wp;     stride = 0;  acc = 0.f; }

#pragma unroll 8
    for (int k = 0; k < HH; k++)
        acc = fmaf(s[k], wptr[(size_t)k * stride], acc);

    float lv = (l < AA) ? acc : -INFINITY;
    float m = lv;
#pragma unroll
    for (int o = 16; o > 0; o >>= 1) m = fmaxf(m, __shfl_xor_sync(0xffffffffu, m, o));
    float e = (l < AA) ? __expf(acc - m) : 0.f;
    float ssum = e;
#pragma unroll
    for (int o = 16; o > 0; o >>= 1) ssum += __shfl_xor_sync(0xffffffffu, ssum, o);

    if (l < AA)  out[(size_t)warp * AA + l] = e / ssum;       // policy
    if (l == AA) out[(size_t)TT * AA + warp] = acc;           // value
}

__global__ void ht_k(const float* __restrict__ seq, float* __restrict__ out) {
    int i = threadIdx.x;
    out[(size_t)TT * (AA + 1) + i] = seq[(size_t)(TT - 1) * HH + i];
}

// ---------------- launch --------------------------------------------------------
extern "C" void kernel_launch(void* const* d_in, const int* in_sizes, int n_in,
                              void* d_out, int out_size)
{
    const float* x  = (const float*)d_in[0];
    const float* h0 = (const float*)d_in[1];
    const float* W1 = (const float*)d_in[2];
    const float* b1 = (const float*)d_in[3];
    const float* W2 = (const float*)d_in[4];
    const float* b2 = (const float*)d_in[5];
    const float* Wg = (const float*)d_in[6];
    const float* Ug = (const float*)d_in[7];
    const float* bg = (const float*)d_in[8];
    const float* Wp = (const float*)d_in[9];
    const float* bp = (const float*)d_in[10];
    const float* Wv = (const float*)d_in[11];
    const float* bv = (const float*)d_in[12];
    float* out = (float*)d_out;

    float *z1, *z2, *X, *seq;
    cudaGetSymbolAddress((void**)&z1,  g_z1);
    cudaGetSymbolAddress((void**)&z2,  g_z2);
    cudaGetSymbolAddress((void**)&X,   g_X);
    cudaGetSymbolAddress((void**)&seq, g_seq);

    cudaFuncSetAttribute(gru_cluster_k,
                         cudaFuncAttributeNonPortableClusterSizeAllowed, 1);

    // 1) MLP front-end + GRU input projection
    dim3 g1(DD / 128, TT / 128);
    sgemm128<<<g1, 256>>>(x,  W1, b1, z1, TT, DD, DIN, 1);
    sgemm128<<<g1, 256>>>(z1, W2, b2, z2, TT, DD, DD, 1);
    dim3 g3((3 * HH) / 128, TT / 128);
    sgemm128<<<g3, 256>>>(z2, Wg, bg /*row 0*/, X, TT, 3 * HH, DD, 0);

    // 2) sequential GRU scan (single 16-CTA cluster, st.async + mbarrier)
    gru_cluster_k<<<CL, THR>>>(X, Ug, bg, h0, seq);

    // 3) heads + final hidden state
    head_k<<<(TT * 32 + 255) / 256, 256>>>(seq, Wp, bp, Wv, bv, out);
    ht_k<<<1, HH>>>(seq, out);
}

// round 12
// speedup vs baseline: 8.8981x; 1.0405x over previous
#include <cuda_runtime.h>
#include <math.h>

#define TT   8192
#define DIN  2048
#define DD   512
#define HH   512
#define AA   18

#define CL   16      // cluster size (CTAs)
#define THR  512     // threads per CTA
#define NW   (THR/32)

// ---------------- scratch ------------------------------------------------------
__device__ float g_z1 [TT * DD];
__device__ float g_z2 [TT * DD];
__device__ float g_X  [TT * 3 * HH];
__device__ float g_seq[TT * HH];

// ---------------- asm helpers --------------------------------------------------
__device__ __forceinline__ unsigned smem_u32(const void* p) {
    unsigned a;
    asm("{ .reg .u64 t; cvta.to.shared.u64 t, %1; cvt.u32.u64 %0, t; }" : "=r"(a) : "l"(p));
    return a;
}
__device__ __forceinline__ unsigned ctarank() {
    unsigned r; asm("mov.u32 %0, %%cluster_ctarank;" : "=r"(r)); return r;
}
__device__ __forceinline__ unsigned mapa_u32(unsigned addr, unsigned rank) {
    unsigned r; asm("mapa.shared::cluster.u32 %0, %1, %2;" : "=r"(r) : "r"(addr), "r"(rank));
    return r;
}
__device__ __forceinline__ unsigned long long pk2(float lo, float hi) {
    unsigned long long r; asm("mov.b64 %0, {%1,%2};" : "=l"(r) : "f"(lo), "f"(hi)); return r;
}
__device__ __forceinline__ void up2(unsigned long long v, float& lo, float& hi) {
    asm("mov.b64 {%0,%1}, %2;" : "=f"(lo), "=f"(hi) : "l"(v));
}
__device__ __forceinline__ unsigned long long ffma2(unsigned long long a,
                                                    unsigned long long b,
                                                    unsigned long long c) {
    unsigned long long d;
    asm("fma.rn.f32x2 %0, %1, %2, %3;" : "=l"(d) : "l"(a), "l"(b), "l"(c));
    return d;
}
// sigmoid: MUFU.EX2-based exp + rcp.approx (avoids div.rn expansion)
__device__ __forceinline__ float sigmoid_rcp(float x) {
    float e = __expf(-x);
    float r;
    asm("rcp.approx.f32 %0, %1;" : "=f"(r) : "f"(1.0f + e));
    return r;
}
// mbarrier primitives
__device__ __forceinline__ void mbar_init(unsigned addr, unsigned cnt) {
    asm volatile("mbarrier.init.shared::cta.b64 [%0], %1;" :: "r"(addr), "r"(cnt) : "memory");
}
__device__ __forceinline__ void mbar_arm(unsigned addr, unsigned txbytes) {
    asm volatile("mbarrier.arrive.expect_tx.shared::cta.b64 _, [%0], %1;"
                 :: "r"(addr), "r"(txbytes) : "memory");
}
__device__ __forceinline__ void mbar_wait(unsigned addr, unsigned parity) {
    asm volatile(
        "{\n\t.reg .pred P;\n"
        "LW_%=:\n\t"
        "mbarrier.try_wait.parity.acquire.cluster.shared::cta.b64 P, [%0], %1, 0x989680;\n\t"
        "@P bra LD_%=;\n\t"
        "bra LW_%=;\n"
        "LD_%=:\n\t}"
        :: "r"(addr), "r"(parity) : "memory");
}
__device__ __forceinline__ void st_async64(unsigned daddr, unsigned long long v,
                                           unsigned maddr) {
    asm volatile("st.async.shared::cluster.mbarrier::complete_tx::bytes.b64 [%0], %1, [%2];"
                 :: "r"(daddr), "l"(v), "r"(maddr) : "memory");
}

// ---------------- 128x128x8 register-blocked SGEMM -----------------------------
__global__ __launch_bounds__(256) void sgemm128(
    const float* __restrict__ A, const float* __restrict__ B,
    const float* __restrict__ bias, float* __restrict__ C,
    int M, int N, int K, int relu)
{
    __shared__ float As[8][128];
    __shared__ float Bs[8][128];
    int tid  = threadIdx.x;
    int brow = blockIdx.y * 128, bcol = blockIdx.x * 128;
    int aRow = tid >> 1,   aCol = (tid & 1) * 4;
    int bRow = tid >> 5,   bCol = (tid & 31) * 4;
    int trow = (tid >> 4) * 8, tcol = (tid & 15) * 8;

    const float* Ap = A + (size_t)(brow + aRow) * K + aCol;
    const float* Bp = B + (size_t)bRow * N + bcol + bCol;

    float acc[8][8];
#pragma unroll
    for (int i = 0; i < 8; i++)
#pragma unroll
        for (int j = 0; j < 8; j++) acc[i][j] = 0.f;

    for (int k0 = 0; k0 < K; k0 += 8) {
        float4 a4 = *(const float4*)Ap;  Ap += 8;
        float4 b4 = *(const float4*)Bp;  Bp += (size_t)8 * N;
        As[aCol + 0][aRow] = a4.x;
        As[aCol + 1][aRow] = a4.y;
        As[aCol + 2][aRow] = a4.z;
        As[aCol + 3][aRow] = a4.w;
        *(float4*)&Bs[bRow][bCol] = b4;
        __syncthreads();
#pragma unroll
        for (int kk = 0; kk < 8; kk++) {
            float fa[8], fb[8];
            *(float4*)&fa[0] = *(const float4*)&As[kk][trow];
            *(float4*)&fa[4] = *(const float4*)&As[kk][trow + 4];
            *(float4*)&fb[0] = *(const float4*)&Bs[kk][tcol];
            *(float4*)&fb[4] = *(const float4*)&Bs[kk][tcol + 4];
#pragma unroll
            for (int i = 0; i < 8; i++)
#pragma unroll
                for (int j = 0; j < 8; j++)
                    acc[i][j] = fmaf(fa[i], fb[j], acc[i][j]);
        }
        __syncthreads();
    }

#pragma unroll
    for (int i = 0; i < 8; i++) {
        float* cp = C + (size_t)(brow + trow + i) * N + bcol + tcol;
#pragma unroll
        for (int j = 0; j < 8; j++) {
            float v = acc[i][j] + bias[bcol + tcol + j];
            if (relu) v = v > 0.f ? v : 0.f;
            cp[j] = v;
        }
    }
}

// ---------------- GRU scan: 16-CTA cluster, st.async + mbarrier ----------------
// 256 warps cluster-wide; warp W owns hidden i0=2W, i1=2W+1 (6 gate columns),
// weights register-resident packed f32x2 (lane l covers k = 4l+128j .. +3).
// h double-buffered in SMEM; each step every warp pushes packed (h[i0],h[i1])
// to all 16 CTAs via st.async.b64 + mbarrier complete_tx (2048 bytes/CTA).
// Loop unrolled x2: even steps read hbuf[0]/push hbuf[1], odd steps reverse.
// X rows prefetched one full step ahead into registers.
__global__ void __cluster_dims__(CL, 1, 1) __launch_bounds__(THR, 1)
gru_cluster_k(const float* __restrict__ X,   // [T, 3H]
              const float* __restrict__ Ug,  // [H, 3H]
              const float* __restrict__ bg,  // [2, 3H]
              const float* __restrict__ h0,  // [1, H]
              float* __restrict__ seq)       // [T, H]
{
    __shared__ __align__(16) float hbuf[2][HH];
    __shared__ __align__(8) unsigned long long mbar[2];

    const int tid = threadIdx.x;
    const int wid = tid >> 5;
    const int l   = tid & 31;
    const unsigned rank = ctarank();
    const int W  = (int)rank * NW + wid;   // 0..255
    const int i0 = 2 * W;
    const int half = l >> 4;               // 0: finalize i0, 1: finalize i1
    const int col  = i0 + half;

    // ---- register-resident packed weights (float4-load friendly layout)
    unsigned long long wp[6][8];
    {
        const int i1 = i0 + 1;
        const int cols[6] = { i0, 512 + i0, 1024 + i0, i1, 512 + i1, 1024 + i1 };
#pragma unroll
        for (int j = 0; j < 4; j++) {
            int k = 4 * l + 128 * j;
            const float* r0 = Ug + (size_t)k * 1536;
            const float* r1 = r0 + 1536;
            const float* r2 = r1 + 1536;
            const float* r3 = r2 + 1536;
#pragma unroll
            for (int g = 0; g < 6; g++) {
                wp[g][2 * j]     = pk2(r0[cols[g]], r1[cols[g]]);
                wp[g][2 * j + 1] = pk2(r2[cols[g]], r3[cols[g]]);
            }
        }
    }

    const float brz = bg[1536 + col];
    const float brr = bg[1536 + 512 + col];
    const float brh = bg[1536 + 1024 + col];

    // remote addresses: lane l (<16) pushes packed (h[i0],h[i1]) to peer l
    const unsigned peer = (unsigned)(l & 15);
    const unsigned rd0 = mapa_u32(smem_u32(&hbuf[0][i0]), peer);
    const unsigned rd1 = mapa_u32(smem_u32(&hbuf[1][i0]), peer);
    const unsigned rm0 = mapa_u32(smem_u32(&mbar[0]), peer);
    const unsigned rm1 = mapa_u32(smem_u32(&mbar[1]), peer);
    const unsigned lm0 = smem_u32(&mbar[0]);
    const unsigned lm1 = smem_u32(&mbar[1]);

    if (tid == 0) {
        mbar_init(lm0, 1);
        mbar_init(lm1, 1);
        mbar_arm(lm0, 2048);   // phase 0 of each buffer
        mbar_arm(lm1, 2048);
        asm volatile("fence.mbarrier_init.release.cluster;" ::: "memory");
    }
    hbuf[0][tid] = h0[tid];
    __syncthreads();
    asm volatile("barrier.cluster.arrive.aligned;" ::: "memory");
    asm volatile("barrier.cluster.wait.aligned;"   ::: "memory");

    // one-step body: dot against hrow, gates, return hn for this lane's col
    auto gates = [&](const float* hrow, float xz, float xr, float xh) -> float {
        const float hprev = hrow[col];
        unsigned long long a0 = 0, a1 = 0, a2 = 0, a3 = 0, a4 = 0, a5 = 0;
        const float4* h4p = (const float4*)hrow + l;   // float4 #l -> floats 4l..4l+3
#pragma unroll
        for (int j = 0; j < 4; j++) {
            float4 h4 = h4p[32 * j];
            unsigned long long hA = pk2(h4.x, h4.y);
            unsigned long long hB = pk2(h4.z, h4.w);
            a0 = ffma2(wp[0][2 * j], hA, a0);
            a1 = ffma2(wp[1][2 * j], hA, a1);
            a2 = ffma2(wp[2][2 * j], hA, a2);
            a3 = ffma2(wp[3][2 * j], hA, a3);
            a4 = ffma2(wp[4][2 * j], hA, a4);
            a5 = ffma2(wp[5][2 * j], hA, a5);
            a0 = ffma2(wp[0][2 * j + 1], hB, a0);
            a1 = ffma2(wp[1][2 * j + 1], hB, a1);
            a2 = ffma2(wp[2][2 * j + 1], hB, a2);
            a3 = ffma2(wp[3][2 * j + 1], hB, a3);
            a4 = ffma2(wp[4][2 * j + 1], hB, a4);
            a5 = ffma2(wp[5][2 * j + 1], hB, a5);
        }
        float s0, s1, s2, s3, s4, s5;
        { float lo, hi;
          up2(a0, lo, hi); s0 = lo + hi;
          up2(a1, lo, hi); s1 = lo + hi;
          up2(a2, lo, hi); s2 = lo + hi;
          up2(a3, lo, hi); s3 = lo + hi;
          up2(a4, lo, hi); s4 = lo + hi;
          up2(a5, lo, hi); s5 = lo + hi; }

        // folded warp reduction
        s0 += __shfl_xor_sync(0xffffffffu, s0, 16);
        s1 += __shfl_xor_sync(0xffffffffu, s1, 16);
        s2 += __shfl_xor_sync(0xffffffffu, s2, 16);
        s3 += __shfl_xor_sync(0xffffffffu, s3, 16);
        s4 += __shfl_xor_sync(0xffffffffu, s4, 16);
        s5 += __shfl_xor_sync(0xffffffffu, s5, 16);
        float uz = half ? s3 : s0;
        float ur = half ? s4 : s1;
        float uh = half ? s5 : s2;
#pragma unroll
        for (int o = 8; o > 0; o >>= 1) {
            uz += __shfl_xor_sync(0xffffffffu, uz, o);
            ur += __shfl_xor_sync(0xffffffffu, ur, o);
            uh += __shfl_xor_sync(0xffffffffu, uh, o);
        }

        const float zt = sigmoid_rcp(xz + uz + brz);
        const float rt = sigmoid_rcp(xr + ur + brr);
        const float hc = sigmoid_rcp(xh + rt * (uh + brh));
        return zt * hprev + (1.f - zt) * hc;
    };

    // X regs for the current step (t=0 preloaded)
    float xz = X[col], xr = X[512 + col], xh = X[1024 + col];
    unsigned ph = 0;

    for (int t = 0; t < TT; t += 2) {
        // ===== step A (t): read hbuf[0], push into hbuf[1] =====
        // prefetch X row t+1 (full-step-ahead cover)
        const float* xpn = X + (size_t)(t + 1) * 1536 + col;
        float nxz = xpn[0], nxr = xpn[512], nxh = xpn[1024];

        if (t) { mbar_wait(lm0, ph ^ 1); if (tid == 0) mbar_arm(lm0, 2048); }

        float hn = gates(hbuf[0], xz, xr, xh);
        {
            const float hn1 = __shfl_down_sync(0xffffffffu, hn, 16);
            if (l < 16) st_async64(rd1, pk2(hn, hn1), rm1);
            if ((l & 15) == 0) seq[(size_t)t * HH + col] = hn;
        }
        xz = nxz; xr = nxr; xh = nxh;

        // ===== step B (t+1): read hbuf[1], push into hbuf[0] =====
        // prefetch X row t+2 (clamped at the tail)
        const int tn = (t + 2 < TT) ? (t + 2) : (TT - 1);
        const float* xpn2 = X + (size_t)tn * 1536 + col;
        nxz = xpn2[0]; nxr = xpn2[512]; nxh = xpn2[1024];

        mbar_wait(lm1, ph); if (tid == 0) mbar_arm(lm1, 2048);

        hn = gates(hbuf[1], xz, xr, xh);
        {
            const float hn1 = __shfl_down_sync(0xffffffffu, hn, 16);
            if (l < 16 && t + 2 < TT) st_async64(rd0, pk2(hn, hn1), rm0);
            if ((l & 15) == 0) seq[(size_t)(t + 1) * HH + col] = hn;
        }
        xz = nxz; xr = nxr; xh = nxh;

        ph ^= 1;
    }

    asm volatile("barrier.cluster.arrive.aligned;" ::: "memory");
    asm volatile("barrier.cluster.wait.aligned;"   ::: "memory");
}

// ---------------- policy / value heads -----------------------------------------
__global__ __launch_bounds__(256) void head_k(
    const float* __restrict__ seq,
    const float* __restrict__ Wp, const float* __restrict__ bp,
    const float* __restrict__ Wv, const float* __restrict__ bv,
    float* __restrict__ out)
{
    int warp = blockIdx.x * (blockDim.x >> 5) + (threadIdx.x >> 5);
    int l = threadIdx.x & 31;
    if (warp >= TT) return;
    const float* s = seq + (size_t)warp * HH;

    const float* wptr;
    int stride;
    float acc;
    if (l < AA)       { wptr = Wp + l; stride = AA; acc = bp[l]; }
    else if (l == AA) { wptr = Wv;     stride = 1;  acc = bv[0]; }
    else              { wptr = Wp;     stride = 0;  acc = 0.f; }

#pragma unroll 8
    for (int k = 0; k < HH; k++)
        acc = fmaf(s[k], wptr[(size_t)k * stride], acc);

    float lv = (l < AA) ? acc : -INFINITY;
    float m = lv;
#pragma unroll
    for (int o = 16; o > 0; o >>= 1) m = fmaxf(m, __shfl_xor_sync(0xffffffffu, m, o));
    float e = (l < AA) ? __expf(acc - m) : 0.f;
    float ssum = e;
#pragma unroll
    for (int o = 16; o > 0; o >>= 1) ssum += __shfl_xor_sync(0xffffffffu, ssum, o);

    if (l < AA)  out[(size_t)warp * AA + l] = e / ssum;       // policy
    if (l == AA) out[(size_t)TT * AA + warp] = acc;           // value
}

__global__ void ht_k(const float* __restrict__ seq, float* __restrict__ out) {
    int i = threadIdx.x;
    out[(size_t)TT * (AA + 1) + i] = seq[(size_t)(TT - 1) * HH + i];
}

// ---------------- launch --------------------------------------------------------
extern "C" void kernel_launch(void* const* d_in, const int* in_sizes, int n_in,
                              void* d_out, int out_size)
{
    const float* x  = (const float*)d_in[0];
    const float* h0 = (const float*)d_in[1];
    const float* W1 = (const float*)d_in[2];
    const float* b1 = (const float*)d_in[3];
    const float* W2 = (const float*)d_in[4];
    const float* b2 = (const float*)d_in[5];
    const float* Wg = (const float*)d_in[6];
    const float* Ug = (const float*)d_in[7];
    const float* bg = (const float*)d_in[8];
    const float* Wp = (const float*)d_in[9];
    const float* bp = (const float*)d_in[10];
    const float* Wv = (const float*)d_in[11];
    const float* bv = (const float*)d_in[12];
    float* out = (float*)d_out;

    float *z1, *z2, *X, *seq;
    cudaGetSymbolAddress((void**)&z1,  g_z1);
    cudaGetSymbolAddress((void**)&z2,  g_z2);
    cudaGetSymbolAddress((void**)&X,   g_X);
    cudaGetSymbolAddress((void**)&seq, g_seq);

    cudaFuncSetAttribute(gru_cluster_k,
                         cudaFuncAttributeNonPortableClusterSizeAllowed, 1);

    // 1) MLP front-end + GRU input projection
    dim3 g1(DD / 128, TT / 128);
    sgemm128<<<g1, 256>>>(x,  W1, b1, z1, TT, DD, DIN, 1);
    sgemm128<<<g1, 256>>>(z1, W2, b2, z2, TT, DD, DD, 1);
    dim3 g3((3 * HH) / 128, TT / 128);
    sgemm128<<<g3, 256>>>(z2, Wg, bg /*row 0*/, X, TT, 3 * HH, DD, 0);

    // 2) sequential GRU scan (single 16-CTA cluster, st.async + mbarrier)
    gru_cluster_k<<<CL, THR>>>(X, Ug, bg, h0, seq);

    // 3) heads + final hidden state
    head_k<<<(TT * 32 + 255) / 256, 256>>>(seq, Wp, bp, Wv, bv, out);
    ht_k<<<1, HH>>>(seq, out);
}